// round 6
// baseline (speedup 1.0000x reference)
#include <cuda_runtime.h>
#include <cuda_bf16.h>
#include <math.h>
#include <stdint.h>

typedef unsigned long long ull;

#define T 8
#define NN 4096
#define F 256
#define FF (F*F)          // 65536
#define NF (NN*F)         // 1048576
#define NSPLIT 8
#define GRU_GRID 128

// ---------------- scratch (static device memory; no allocations) -----------
__device__ float g_zt[T*FF];
__device__ float g_P[3*T*FF];
__device__ float g_Q[FF];
__device__ float g_Qseq[T*FF];
__device__ float g_W3[3*FF];
__device__ float g_upd[FF];
__device__ float g_RQ[FF];
__device__ float g_th[T*F];
__device__ float g_Y[T*NF];
__device__ float g_part[7*NSPLIT*FF];
__device__ float g_h1top[T*FF];
__device__ float g_h1full[NF];
__device__ float g_Z[NF];
__device__ unsigned g_bar[64];
__device__ __nv_bfloat16 g_Ah[(long)NN*NN];   // 32MB
__device__ __nv_bfloat16 g_Al[(long)NN*NN];   // 32MB
__device__ __nv_bfloat16 g_Bh[F*NN];          // 2MB  (transposed split of Y7 / Z)
__device__ __nv_bfloat16 g_Bl[F*NN];

// ---------------- f32x2 helpers --------------------------------------------
__device__ __forceinline__ ull pk2(float lo, float hi) {
    ull r; asm("mov.b64 %0, {%1, %2};" : "=l"(r) : "f"(lo), "f"(hi)); return r;
}
__device__ __forceinline__ float lo32(ull v){ return __uint_as_float((unsigned)v); }
__device__ __forceinline__ float hi32(ull v){ return __uint_as_float((unsigned)(v >> 32)); }
#define FMA2(acc, a, b) asm("fma.rn.f32x2 %0, %1, %2, %0;" : "+l"(acc) : "l"(a), "l"(b))

__device__ __forceinline__ uint32_t smem_u32(const void* p) {
    uint32_t a;
    asm("{ .reg .u64 t; cvta.to.shared.u64 t, %1; cvt.u32.u64 %0, t; }" : "=r"(a) : "l"(p));
    return a;
}

// ---------------- mma.sync helpers ------------------------------------------
#define LDM_X4(r0, r1, r2, r3, addr) \
    asm volatile("ldmatrix.sync.aligned.m8n8.x4.shared.b16 {%0,%1,%2,%3}, [%4];" \
        : "=r"(r0), "=r"(r1), "=r"(r2), "=r"(r3) : "r"(addr))

#define MMA16816(d, a, b0, b1) \
    asm volatile("mma.sync.aligned.m16n8k16.row.col.f32.bf16.bf16.f32 " \
        "{%0,%1,%2,%3}, {%4,%5,%6,%7}, {%8,%9}, {%0,%1,%2,%3};" \
        : "+f"((d)[0]), "+f"((d)[1]), "+f"((d)[2]), "+f"((d)[3]) \
        : "r"((a)[0]), "r"((a)[1]), "r"((a)[2]), "r"((a)[3]), "r"(b0), "r"(b1))

// ---------------- split-bf16 GEMM via legacy mma.sync (HMMA) ----------------
// C[4096,256] (+relu) = Ah@Bh + Ah@Bl + Al@Bh
// A* [4096,4096] bf16 row-major; B* [256,4096] bf16 (B[n,k] = origB[k,n]).
// grid (4, 32): CTA tile 128m x 64n. 8 warps, warp tile 32x32.
__global__ void __launch_bounds__(256, 1) gemm_mma(
    const __nv_bfloat16* __restrict__ Ahp, const __nv_bfloat16* __restrict__ Alp,
    const __nv_bfloat16* __restrict__ Bhp, const __nv_bfloat16* __restrict__ Blp,
    float* __restrict__ C, int act)
{
    __shared__ __align__(16) __nv_bfloat16 sA[2][128][40];   // 80B rows (bank-safe)
    __shared__ __align__(16) __nv_bfloat16 sB[2][64][40];

    const int tid = threadIdx.x;
    const int wid = tid >> 5, lane = tid & 31;
    const int wm = wid & 3, wn = wid >> 2;        // warp grid 4m x 2n
    const long bm = (long)blockIdx.y << 7;
    const int  bn = blockIdx.x << 6;

    // global->smem segment mapping (16B each)
    const int ar0 = tid >> 1;                     // A rows: 2 segs per thread? no:
    // A tile: 128 rows x 4 segs = 512 segs; threads handle s=tid and s=tid+256.
    const int as0r = tid >> 2,        as0o = (tid & 3) << 3;
    const int as1r = (tid + 256) >> 2, as1o = ((tid + 256) & 3) << 3;
    const int bsr  = tid >> 2,        bso  = (tid & 3) << 3;
    (void)ar0;

    // ldmatrix lane addressing
    const int aRow = wm * 32 + (lane & 15);
    const int aCol = ((lane >> 4) & 1) << 3;
    const int bRow = wn * 32 + (((lane >> 4) & 1) << 3) + (lane & 7);
    const int bCol = ((lane >> 3) & 1) << 3;
    const uint32_t sAu = smem_u32(&sA[0][0][0]);
    const uint32_t sBu = smem_u32(&sB[0][0][0]);
    const uint32_t aBase = sAu + (uint32_t)(aRow * 40 + aCol) * 2u;
    const uint32_t bBase = sBu + (uint32_t)(bRow * 40 + bCol) * 2u;
    const uint32_t ABUF = 128 * 40 * 2, BBUF = 64 * 40 * 2;

    float acc[2][4][4];
#pragma unroll
    for (int mi = 0; mi < 2; ++mi)
#pragma unroll
        for (int nj = 0; nj < 4; ++nj)
#pragma unroll
            for (int e = 0; e < 4; ++e) acc[mi][nj][e] = 0.f;

    // prologue: chunk 0 (pass 0: Ah, Bh)
    {
        *(int4*)&sA[0][as0r][as0o] = *(const int4*)(Ahp + (bm + as0r) * (long)NN + as0o);
        *(int4*)&sA[0][as1r][as1o] = *(const int4*)(Ahp + (bm + as1r) * (long)NN + as1o);
        *(int4*)&sB[0][bsr][bso]   = *(const int4*)(Bhp + (long)(bn + bsr) * NN + bso);
    }
    __syncthreads();

    int buf = 0;
    const int NITER = 384;                        // 3 passes x 128 chunks
    for (int i = 0; i < NITER; ++i) {
        int4 ra0, ra1, rb0;
        const bool more = (i + 1 < NITER);
        if (more) {
            const int ni = i + 1;
            const int p = ni >> 7;
            const long kc = (long)(ni & 127) << 5;
            const __nv_bfloat16* Ag = (p == 2) ? Alp : Ahp;
            const __nv_bfloat16* Bg = (p == 1) ? Blp : Bhp;
            ra0 = *(const int4*)(Ag + (bm + as0r) * (long)NN + kc + as0o);
            ra1 = *(const int4*)(Ag + (bm + as1r) * (long)NN + kc + as1o);
            rb0 = *(const int4*)(Bg + (long)(bn + bsr) * NN + kc + bso);
        }
        // compute current buffer
        const uint32_t aB = aBase + buf * ABUF;
        const uint32_t bB = bBase + buf * BBUF;
#pragma unroll
        for (int ks = 0; ks < 2; ++ks) {
            uint32_t a[2][4], b[2][4];
            LDM_X4(a[0][0], a[0][1], a[0][2], a[0][3], aB + (ks * 16) * 2);
            LDM_X4(a[1][0], a[1][1], a[1][2], a[1][3], aB + (16 * 40 + ks * 16) * 2);
            LDM_X4(b[0][0], b[0][1], b[0][2], b[0][3], bB + (ks * 16) * 2);
            LDM_X4(b[1][0], b[1][1], b[1][2], b[1][3], bB + (16 * 40 + ks * 16) * 2);
#pragma unroll
            for (int mi = 0; mi < 2; ++mi) {
#pragma unroll
                for (int nj = 0; nj < 4; ++nj) {
                    MMA16816(acc[mi][nj], a[mi],
                             b[nj >> 1][(nj & 1) * 2], b[nj >> 1][(nj & 1) * 2 + 1]);
                }
            }
        }
        if (more) {
            const int nb = buf ^ 1;
            *(int4*)&sA[nb][as0r][as0o] = ra0;
            *(int4*)&sA[nb][as1r][as1o] = ra1;
            *(int4*)&sB[nb][bsr][bso]   = rb0;
        }
        __syncthreads();
        buf ^= 1;
    }

    // epilogue
#pragma unroll
    for (int mi = 0; mi < 2; ++mi) {
#pragma unroll
        for (int nj = 0; nj < 4; ++nj) {
            const long row0 = bm + wm * 32 + mi * 16 + (lane >> 2);
            const int  col  = bn + wn * 32 + nj * 8 + (lane & 3) * 2;
            float2 v0 = make_float2(acc[mi][nj][0], acc[mi][nj][1]);
            float2 v1 = make_float2(acc[mi][nj][2], acc[mi][nj][3]);
            if (act) {
                v0.x = fmaxf(v0.x, 0.f); v0.y = fmaxf(v0.y, 0.f);
                v1.x = fmaxf(v1.x, 0.f); v1.y = fmaxf(v1.y, 0.f);
            }
            *(float2*)&C[row0 * (long)F + col]       = v0;
            *(float2*)&C[(row0 + 8) * (long)F + col] = v1;
        }
    }
}

// ---------------- conversion kernels ----------------------------------------
__global__ void asplit(const float* __restrict__ A,
                       __nv_bfloat16* __restrict__ Ah, __nv_bfloat16* __restrict__ Al)
{
    long i = ((long)blockIdx.x * 256 + threadIdx.x) * 4;
    float4 v = *(const float4*)(A + i);
    __nv_bfloat16 h0 = __float2bfloat16(v.x), h1 = __float2bfloat16(v.y);
    __nv_bfloat16 h2 = __float2bfloat16(v.z), h3 = __float2bfloat16(v.w);
    __nv_bfloat162 hh0(h0, h1), hh1(h2, h3);
    *(__nv_bfloat162*)(Ah + i)     = hh0;
    *(__nv_bfloat162*)(Ah + i + 2) = hh1;
    __nv_bfloat162 ll0(__float2bfloat16(v.x - __bfloat162float(h0)),
                       __float2bfloat16(v.y - __bfloat162float(h1)));
    __nv_bfloat162 ll1(__float2bfloat16(v.z - __bfloat162float(h2)),
                       __float2bfloat16(v.w - __bfloat162float(h3)));
    *(__nv_bfloat162*)(Al + i)     = ll0;
    *(__nv_bfloat162*)(Al + i + 2) = ll1;
}

__global__ void tsplit(const float* __restrict__ Y,
                       __nv_bfloat16* __restrict__ Bh, __nv_bfloat16* __restrict__ Bl)
{
    __shared__ float tb[32][33];
    const int k0 = blockIdx.x * 32, n0 = blockIdx.y * 32;
    const int tx = threadIdx.x & 31, ty = threadIdx.x >> 5;
#pragma unroll
    for (int r = ty; r < 32; r += 8)
        tb[r][tx] = Y[(long)(k0 + r) * F + n0 + tx];
    __syncthreads();
#pragma unroll
    for (int c = ty; c < 32; c += 8) {
        float v = tb[tx][c];
        __nv_bfloat16 h = __float2bfloat16(v);
        Bh[(long)(n0 + c) * NN + k0 + tx] = h;
        Bl[(long)(n0 + c) * NN + k0 + tx] = __float2bfloat16(v - __bfloat162float(h));
    }
}

// ---------------- big GEMM: 128x64 tile, FFMA2, double-buffered -------------
__global__ void __launch_bounds__(256, 2) gemm_big(
    const float* __restrict__ Ab, const float* __restrict__ Bb, float* __restrict__ Cb,
    int K, int lda, int ldb, int ldc,
    long sA_, long sB_, long sC_, int act, int mode)
{
    const int z = blockIdx.z;
    const float* A; const float* B; float* C;
    if (mode == 0)      { A = Ab + z * sA_; B = Bb + z * sB_; C = Cb + z * sC_; }
    else if (mode == 1) { A = Ab + (long)(z >> 3) * sA_; B = Bb + (long)(z & 7) * sB_; C = Cb + (long)z * sC_; }
    else                { int t = z >> 3, s = z & 7;
                          A = Ab + (long)t * sA_ + (long)s * K;
                          B = Bb + (long)t * sB_ + (long)s * K * ldb;
                          C = Cb + (long)z * sC_; }

    __shared__ float As[2][16][136];
    __shared__ float Bs[2][16][64];

    const int tid = threadIdx.x;
    const int tx = tid & 15, ty = tid >> 4;
    const long bm = (long)blockIdx.y << 7;
    const int  bn = blockIdx.x << 6;

    const int a_row = tid >> 2;
    const int a_kc  = (tid & 3) << 2;
    const int b_kr  = tid >> 4;
    const int b_kc  = (tid & 15) << 2;

    const float* Ap0 = A + (bm + a_row) * (long)lda + a_kc;
    const float* Ap1 = Ap0 + (long)64 * lda;
    const float* Bp  = B + (long)b_kr * ldb + bn + b_kc;

    {
        float4 va0 = *(const float4*)Ap0;
        float4 va1 = *(const float4*)Ap1;
        float4 vb  = *(const float4*)Bp;
        As[0][a_kc+0][a_row] = va0.x; As[0][a_kc+1][a_row] = va0.y;
        As[0][a_kc+2][a_row] = va0.z; As[0][a_kc+3][a_row] = va0.w;
        As[0][a_kc+0][a_row+64] = va1.x; As[0][a_kc+1][a_row+64] = va1.y;
        As[0][a_kc+2][a_row+64] = va1.z; As[0][a_kc+3][a_row+64] = va1.w;
        *(float4*)&Bs[0][b_kr][b_kc] = vb;
    }
    __syncthreads();

    ull acc[4][4];
#pragma unroll
    for (int p = 0; p < 4; p++)
#pragma unroll
        for (int j = 0; j < 4; j++) acc[p][j] = 0ULL;

    const int nIter = K >> 4;
    int buf = 0;
    for (int it = 0; it < nIter; ++it) {
        float4 na0, na1, nb;
        const bool more = (it + 1 < nIter);
        if (more) {
            na0 = *(const float4*)(Ap0 + (it + 1) * 16);
            na1 = *(const float4*)(Ap1 + (it + 1) * 16);
            nb  = *(const float4*)(Bp + (long)(it + 1) * 16 * ldb);
        }
#pragma unroll
        for (int k = 0; k < 16; ++k) {
            ull a0 = *(const ull*)&As[buf][k][(ty<<3) + 0];
            ull a1 = *(const ull*)&As[buf][k][(ty<<3) + 2];
            ull a2 = *(const ull*)&As[buf][k][(ty<<3) + 4];
            ull a3 = *(const ull*)&As[buf][k][(ty<<3) + 6];
            float4 bv = *(const float4*)&Bs[buf][k][tx<<2];
            ull b0 = pk2(bv.x, bv.x), b1 = pk2(bv.y, bv.y);
            ull b2 = pk2(bv.z, bv.z), b3 = pk2(bv.w, bv.w);
            FMA2(acc[0][0], a0, b0); FMA2(acc[0][1], a0, b1); FMA2(acc[0][2], a0, b2); FMA2(acc[0][3], a0, b3);
            FMA2(acc[1][0], a1, b0); FMA2(acc[1][1], a1, b1); FMA2(acc[1][2], a1, b2); FMA2(acc[1][3], a1, b3);
            FMA2(acc[2][0], a2, b0); FMA2(acc[2][1], a2, b1); FMA2(acc[2][2], a2, b2); FMA2(acc[2][3], a2, b3);
            FMA2(acc[3][0], a3, b0); FMA2(acc[3][1], a3, b1); FMA2(acc[3][2], a3, b2); FMA2(acc[3][3], a3, b3);
        }
        if (more) {
            const int nbuf = buf ^ 1;
            As[nbuf][a_kc+0][a_row] = na0.x; As[nbuf][a_kc+1][a_row] = na0.y;
            As[nbuf][a_kc+2][a_row] = na0.z; As[nbuf][a_kc+3][a_row] = na0.w;
            As[nbuf][a_kc+0][a_row+64] = na1.x; As[nbuf][a_kc+1][a_row+64] = na1.y;
            As[nbuf][a_kc+2][a_row+64] = na1.z; As[nbuf][a_kc+3][a_row+64] = na1.w;
            *(float4*)&Bs[nbuf][b_kr][b_kc] = nb;
        }
        __syncthreads();
        buf ^= 1;
    }

#pragma unroll
    for (int p = 0; p < 4; ++p) {
        float4 vlo = make_float4(lo32(acc[p][0]), lo32(acc[p][1]), lo32(acc[p][2]), lo32(acc[p][3]));
        float4 vhi = make_float4(hi32(acc[p][0]), hi32(acc[p][1]), hi32(acc[p][2]), hi32(acc[p][3]));
        if (act) {
            vlo.x = fmaxf(vlo.x, 0.f); vlo.y = fmaxf(vlo.y, 0.f);
            vlo.z = fmaxf(vlo.z, 0.f); vlo.w = fmaxf(vlo.w, 0.f);
            vhi.x = fmaxf(vhi.x, 0.f); vhi.y = fmaxf(vhi.y, 0.f);
            vhi.z = fmaxf(vhi.z, 0.f); vhi.w = fmaxf(vhi.w, 0.f);
        }
        long r = bm + (ty << 3) + (p << 1);
        *(float4*)&C[r * (long)ldc + bn + (tx << 2)]       = vlo;
        *(float4*)&C[(r + 1) * (long)ldc + bn + (tx << 2)] = vhi;
    }
}

// ---------------- persistent GRU chain --------------------------------------
__device__ __forceinline__ void grid_bar(unsigned* ctr, unsigned nblk) {
    __syncthreads();
    if (threadIdx.x == 0) {
        __threadfence();
        unsigned prev = atomicAdd(ctr, 1u);
        if (prev + 1u < nblk) {
            while (*(volatile unsigned*)ctr < nblk) { }
        }
        __threadfence();
    }
    __syncthreads();
}

__device__ __forceinline__ void tile32(
    const float* __restrict__ gA, const float* __restrict__ gB,
    float (*As)[16][36], float (*Bs)[16][36], ull* acc)
{
    const int tid = threadIdx.x;
    const int ty = tid >> 4, tx = tid & 15;
    acc[0] = 0ULL; acc[1] = 0ULL;

    const int la_r = tid >> 2;
    const int la_k = (tid & 3) << 2;
    const int lb_u = tid & 127;
    const int lb_k = lb_u >> 3;
    const int lb_n = (lb_u & 7) << 2;

    {
        float4 v;
        if (tid < 128) {
            v = *(const float4*)(gA + la_r * F + la_k);
            As[0][la_k+0][la_r] = v.x; As[0][la_k+1][la_r] = v.y;
            As[0][la_k+2][la_r] = v.z; As[0][la_k+3][la_r] = v.w;
        } else {
            v = *(const float4*)(gB + lb_k * F + lb_n);
            *(float4*)&Bs[0][lb_k][lb_n] = v;
        }
    }
    __syncthreads();

    int buf = 0;
    for (int it = 0; it < 16; ++it) {
        float4 nv;
        const bool more = (it < 15);
        if (more) {
            int k0 = (it + 1) << 4;
            if (tid < 128) nv = *(const float4*)(gA + la_r * F + k0 + la_k);
            else           nv = *(const float4*)(gB + (k0 + lb_k) * F + lb_n);
        }
#pragma unroll
        for (int k = 0; k < 16; ++k) {
            ull av = *(const ull*)&As[buf][k][ty << 1];
            ull bv = *(const ull*)&Bs[buf][k][tx << 1];
            float b0 = lo32(bv), b1 = hi32(bv);
            ull bb0 = pk2(b0, b0);
            ull bb1 = pk2(b1, b1);
            FMA2(acc[0], av, bb0);
            FMA2(acc[1], av, bb1);
        }
        if (more) {
            const int nb = buf ^ 1;
            if (tid < 128) {
                As[nb][la_k+0][la_r] = nv.x; As[nb][la_k+1][la_r] = nv.y;
                As[nb][la_k+2][la_r] = nv.z; As[nb][la_k+3][la_r] = nv.w;
            } else {
                *(float4*)&Bs[nb][lb_k][lb_n] = nv;
            }
        }
        __syncthreads();
        buf ^= 1;
    }
}

__device__ __forceinline__ float sigf(float x) { return 1.0f / (1.0f + expf(-x)); }

__global__ void __launch_bounds__(256, 1) gru_chain(
    const float* __restrict__ Uz, const float* __restrict__ Ur, const float* __restrict__ Uh,
    const float* __restrict__ P,
    const float* __restrict__ bz, const float* __restrict__ br, const float* __restrict__ bh,
    const float* __restrict__ Q0, float* __restrict__ Q,
    float* __restrict__ upd, float* __restrict__ RQ,
    float* __restrict__ Qseq, unsigned* __restrict__ bar)
{
    __shared__ float As[2][16][36];
    __shared__ float Bs[2][16][36];

    const int tid = threadIdx.x;
    const int bid = blockIdx.x;
    const int gate = bid >> 6;
    const int id   = bid & 63;
    const int tm   = id >> 3;
    const int tn   = id & 7;
    const int ty = tid >> 4, tx = tid & 15;
    const int rb = tm * 32 + (ty << 1);
    const int cb = tn * 32 + (tx << 1);

    for (int t = 0; t < T; ++t) {
        const float* Qprev = (t == 0) ? Q0 : Q;

        {
            const float* Amat = gate ? Ur : Uz;
            const float* Pg   = P + (long)((gate ? T : 0) + t) * FF;
            const float* bb   = gate ? br : bz;
            ull acc[2];
            tile32(Amat + (long)tm * 32 * F, Qprev + tn * 32, As, Bs, acc);
#pragma unroll
            for (int j = 0; j < 2; ++j) {
#pragma unroll
                for (int e = 0; e < 2; ++e) {
                    long idx = (long)(rb + e) * F + cb + j;
                    float a = e ? hi32(acc[j]) : lo32(acc[j]);
                    float s = sigf(a + Pg[idx] + bb[idx]);
                    if (!gate) upd[idx] = s;
                    else       RQ[idx] = s * Qprev[idx];
                }
            }
        }
        grid_bar(bar + 2 * t, GRU_GRID);

        if (bid < 64) {
            const float* Ph = P + (long)(2 * T + t) * FF;
            ull acc[2];
            tile32(Uh + (long)tm * 32 * F, RQ + tn * 32, As, Bs, acc);
#pragma unroll
            for (int j = 0; j < 2; ++j) {
#pragma unroll
                for (int e = 0; e < 2; ++e) {
                    long idx = (long)(rb + e) * F + cb + j;
                    float a = e ? hi32(acc[j]) : lo32(acc[j]);
                    float h = tanhf(a + Ph[idx] + bh[idx]);
                    float u = upd[idx];
                    float q = (1.0f - u) * Qprev[idx] + u * h;
                    Q[idx] = q;
                    if (Qseq) Qseq[(long)t * FF + idx] = q;
                }
            }
        }
        grid_bar(bar + 2 * t + 1, GRU_GRID);
    }
}

// ---------------- scores + transposed zt ------------------------------------
__global__ void score_kernel(const float* __restrict__ embs, long stride, int ld,
                             const float* __restrict__ scorer, float* __restrict__ th)
{
    const int t = blockIdx.x;
    const float* E = embs + (long)t * stride;
    __shared__ float sc[F];
    __shared__ float red[256];
    const int tid = threadIdx.x;
    float s = scorer[tid];
    sc[tid] = s;
    red[tid] = s * s;
    __syncthreads();
    for (int off = 128; off > 0; off >>= 1) {
        if (tid < off) red[tid] += red[tid + off];
        __syncthreads();
    }
    const float inv_sn = 1.0f / sqrtf(red[0]);
    float dot = 0.f;
    const float* row = E + (long)tid * ld;
#pragma unroll 8
    for (int c = 0; c < F; c++) dot += row[c] * sc[c];
    th[t * F + tid] = tanhf(dot * inv_sn);
}

__global__ void zt_trans(const float* __restrict__ embs, long stride, int ld,
                         const float* __restrict__ th, float* __restrict__ zt)
{
    const int t = blockIdx.y;
    const int tile = blockIdx.x;
    const int ti = tile >> 3, tj = tile & 7;
    const float* E = embs + (long)t * stride;
    float* Z = zt + (long)t * FF;

    __shared__ float tb[32][33];
    const int tx = threadIdx.x & 31;
    const int ty8 = threadIdx.x >> 5;

#pragma unroll
    for (int r0 = 0; r0 < 4; ++r0) {
        int r = ty8 + (r0 << 3);
        tb[r][tx] = E[(long)(ti * 32 + r) * ld + tj * 32 + tx] * th[t * F + ti * 32 + r];
    }
    __syncthreads();
#pragma unroll
    for (int c0 = 0; c0 < 4; ++c0) {
        int c = ty8 + (c0 << 3);
        Z[(long)(tj * 32 + c) * F + ti * 32 + tx] = tb[tx][c];
    }
}

// ---------------- misc -------------------------------------------------------
__global__ void reduce_relu(const float* __restrict__ part, float* __restrict__ out)
{
    long i = (long)blockIdx.x * 256 + threadIdx.x;
    long t = i >> 16;
    long r = i & (FF - 1);
    const float* p = part + t * (long)(NSPLIT * FF) + r;
    float s = 0.f;
#pragma unroll
    for (int j = 0; j < NSPLIT; ++j) s += p[(long)j * FF];
    out[i] = fmaxf(s, 0.0f);
}

__global__ void pack3(const float* __restrict__ a, const float* __restrict__ b,
                      const float* __restrict__ c, float* __restrict__ dst)
{
    int i = blockIdx.x * 256 + threadIdx.x;
    dst[i] = a[i]; dst[FF + i] = b[i]; dst[2 * FF + i] = c[i];
}

__global__ void copy1(const float* __restrict__ src, float* __restrict__ dst)
{
    int i = blockIdx.x * 256 + threadIdx.x;
    dst[i] = src[i];
}

__global__ void zero_bar(unsigned* b) { b[threadIdx.x] = 0u; }

// ---------------------------------------------------------------------------
extern "C" void kernel_launch(void* const* d_in, const int* in_sizes, int n_in,
                              void* d_out, int out_size)
{
    const float* Aadj = (const float*)d_in[0];
    const float* X    = (const float*)d_in[1];
    auto LP = [&](int l, int idx) { return (const float*)d_in[3 + l * 11 + idx]; };

    float *zt, *P, *Q, *Qseq, *W3, *upd, *RQ, *th, *Y, *part, *h1top, *h1full, *Z;
    unsigned* bar;
    __nv_bfloat16 *Ah, *Al, *Bh, *Bl;
    cudaGetSymbolAddress((void**)&zt,     g_zt);
    cudaGetSymbolAddress((void**)&P,      g_P);
    cudaGetSymbolAddress((void**)&Q,      g_Q);
    cudaGetSymbolAddress((void**)&Qseq,   g_Qseq);
    cudaGetSymbolAddress((void**)&W3,     g_W3);
    cudaGetSymbolAddress((void**)&upd,    g_upd);
    cudaGetSymbolAddress((void**)&RQ,     g_RQ);
    cudaGetSymbolAddress((void**)&th,     g_th);
    cudaGetSymbolAddress((void**)&Y,      g_Y);
    cudaGetSymbolAddress((void**)&part,   g_part);
    cudaGetSymbolAddress((void**)&h1top,  g_h1top);
    cudaGetSymbolAddress((void**)&h1full, g_h1full);
    cudaGetSymbolAddress((void**)&Z,      g_Z);
    cudaGetSymbolAddress((void**)&bar,    g_bar);
    cudaGetSymbolAddress((void**)&Ah,     g_Ah);
    cudaGetSymbolAddress((void**)&Al,     g_Al);
    cudaGetSymbolAddress((void**)&Bh,     g_Bh);
    cudaGetSymbolAddress((void**)&Bl,     g_Bl);

    zero_bar<<<1, 64>>>(bar);
    // split A[7] once
    asplit<<<(int)(((long)NN * NN / 4) / 256), 256>>>(Aadj + 7L * NN * NN, Ah, Al);

    for (int l = 0; l < 2; ++l) {
        const float* embs = (l == 0) ? X : h1top;
        long estride = (l == 0) ? (long)NF : (long)FF;

        score_kernel<<<T, 256>>>(embs, estride, F, LP(l, 0), th);
        zt_trans<<<dim3(64, T), 256>>>(embs, estride, F, th, zt);

        pack3<<<FF / 256, 256>>>(LP(l, 1), LP(l, 4), LP(l, 7), W3);
        gemm_big<<<dim3(4, 2, 24), 256>>>(W3, zt, P, F, F, F, F,
                                          (long)FF, (long)FF, (long)FF, 0, 1);

        gru_chain<<<GRU_GRID, 256>>>(LP(l, 2), LP(l, 5), LP(l, 8), P,
                                     LP(l, 3), LP(l, 6), LP(l, 9),
                                     LP(l, 10), Q, upd, RQ,
                                     (l == 0) ? Qseq : nullptr,
                                     bar + l * 32);

        if (l == 0) {
            // Y[t] = X[t] @ Qseq[t]
            gemm_big<<<dim3(4, 32, 8), 256>>>(X, Qseq, Y, F, F, F, F,
                                              (long)NF, (long)FF, (long)NF, 0, 0);
            // h1top[t] = relu(A[t][:256,:] @ Y[t]), t=0..6, split-K x8
            gemm_big<<<dim3(4, 2, 56), 256>>>(Aadj, Y, part, NN / NSPLIT, NN, F, F,
                                              (long)NN * NN, (long)NF, (long)FF, 0, 2);
            reduce_relu<<<7 * FF / 256, 256>>>(part, h1top);
            // h1full = relu(A[7] @ Y[7])  — mma.sync split-bf16
            tsplit<<<dim3(128, 8), 256>>>(Y + 7L * NF, Bh, Bl);
            gemm_mma<<<dim3(4, 32), 256>>>(Ah, Al, Bh, Bl, h1full, 1);
            copy1<<<FF / 256, 256>>>(h1full, h1top + 7L * FF);
        }
    }

    // out = relu(A[7] @ (h1full @ Q1_final))  — mma.sync split-bf16
    gemm_big<<<dim3(4, 32, 1), 256>>>(h1full, Q, Z, F, F, F, F, 0, 0, 0, 0, 0);
    tsplit<<<dim3(128, 8), 256>>>(Z, Bh, Bl);
    gemm_mma<<<dim3(4, 32), 256>>>(Ah, Al, Bh, Bl, (float*)d_out, 1);
}

// round 7
// speedup vs baseline: 1.1967x; 1.1967x over previous
#include <cuda_runtime.h>
#include <cuda_bf16.h>
#include <math.h>
#include <stdint.h>

typedef unsigned long long ull;

#define T 8
#define NN 4096
#define F 256
#define FF (F*F)          // 65536
#define NF (NN*F)         // 1048576
#define NSPLIT 8
#define GRU_GRID 128

// ---------------- scratch (static device memory; no allocations) -----------
__device__ float g_zt[T*FF];
__device__ float g_P[3*T*FF];
__device__ float g_Q[FF];
__device__ float g_Qseq[T*FF];
__device__ float g_W3[3*FF];
__device__ float g_upd[FF];
__device__ float g_RQ[FF];
__device__ float g_th[T*F];
__device__ float g_Y[T*NF];
__device__ float g_part[7*NSPLIT*FF];
__device__ float g_h1top[T*FF];
__device__ float g_h1full[NF];
__device__ float g_Z[NF];
__device__ unsigned g_bar[64];
__device__ __nv_bfloat16 g_Ah[(long)NN*NN];   // 32MB
__device__ __nv_bfloat16 g_Al[(long)NN*NN];   // 32MB
__device__ __nv_bfloat16 g_Bh[F*NN];          // 2MB
__device__ __nv_bfloat16 g_Bl[F*NN];

// ---------------- f32x2 helpers --------------------------------------------
__device__ __forceinline__ ull pk2(float lo, float hi) {
    ull r; asm("mov.b64 %0, {%1, %2};" : "=l"(r) : "f"(lo), "f"(hi)); return r;
}
__device__ __forceinline__ float lo32(ull v){ return __uint_as_float((unsigned)v); }
__device__ __forceinline__ float hi32(ull v){ return __uint_as_float((unsigned)(v >> 32)); }
#define FMA2(acc, a, b) asm("fma.rn.f32x2 %0, %1, %2, %0;" : "+l"(acc) : "l"(a), "l"(b))

__device__ __forceinline__ uint32_t smem_u32(const void* p) {
    uint32_t a;
    asm("{ .reg .u64 t; cvta.to.shared.u64 t, %1; cvt.u32.u64 %0, t; }" : "=r"(a) : "l"(p));
    return a;
}

// ---------------- mma.sync helpers ------------------------------------------
#define LDM_X4(r0, r1, r2, r3, addr) \
    asm volatile("ldmatrix.sync.aligned.m8n8.x4.shared.b16 {%0,%1,%2,%3}, [%4];" \
        : "=r"(r0), "=r"(r1), "=r"(r2), "=r"(r3) : "r"(addr))

#define MMA16816(d, a, b0, b1) \
    asm volatile("mma.sync.aligned.m16n8k16.row.col.f32.bf16.bf16.f32 " \
        "{%0,%1,%2,%3}, {%4,%5,%6,%7}, {%8,%9}, {%0,%1,%2,%3};" \
        : "+f"((d)[0]), "+f"((d)[1]), "+f"((d)[2]), "+f"((d)[3]) \
        : "r"((a)[0]), "r"((a)[1]), "r"((a)[2]), "r"((a)[3]), "r"(b0), "r"(b1))

#define CP16(dst, src) \
    asm volatile("cp.async.cg.shared.global [%0], [%1], 16;" :: "r"(dst), "l"(src))
#define CP_COMMIT() asm volatile("cp.async.commit_group;" ::: "memory")
#define CP_WAIT1()  asm volatile("cp.async.wait_group 1;" ::: "memory")

// ---------------- split-bf16 GEMM, single-pass 3-term, cp.async 3-stage -----
// C[4096,256](+relu) = Ah@Bh + Ah@Bl + Al@Bh ; A*[4096,4096] bf16 row-major,
// B*[256,4096] bf16 (B[n,k]). grid (4,32): CTA 128m x 64n, 8 warps (4m x 2n).
// Stage layout (bytes): AH@0 (128x40x2=10240), AL@10240, BH@20480 (64x40x2=5120),
// BL@25600; stage stride 30720; 3 stages = 92160 dynamic smem.
__global__ void __launch_bounds__(256, 1) gemm_mma(
    const __nv_bfloat16* __restrict__ Ahp, const __nv_bfloat16* __restrict__ Alp,
    const __nv_bfloat16* __restrict__ Bhp, const __nv_bfloat16* __restrict__ Blp,
    float* __restrict__ C, int act)
{
    extern __shared__ __align__(16) char smem[];
    const uint32_t sm0 = smem_u32(smem);

    const int tid = threadIdx.x;
    const int wid = tid >> 5, lane = tid & 31;
    const int wm = wid & 3, wn = wid >> 2;
    const long bm = (long)blockIdx.y << 7;
    const int  bn = blockIdx.x << 6;

    // ldmatrix lane addressing (byte offsets within a stage)
    const int aRow = wm * 32 + (lane & 15);
    const int aCol = ((lane >> 4) & 1) << 3;
    const int bRow = wn * 32 + (((lane >> 4) & 1) << 3) + (lane & 7);
    const int bCol = ((lane >> 3) & 1) << 3;
    const uint32_t aOff = (uint32_t)(aRow * 40 + aCol) * 2u;          // within AH/AL
    const uint32_t bOff = (uint32_t)(bRow * 40 + bCol) * 2u;          // within BH/BL

    float acc[2][4][4];
#pragma unroll
    for (int mi = 0; mi < 2; ++mi)
#pragma unroll
        for (int nj = 0; nj < 4; ++nj)
#pragma unroll
            for (int e = 0; e < 4; ++e) acc[mi][nj][e] = 0.f;

    // issue one stage's cp.asyncs (6 segs of 16B per thread)
    auto issue = [&](int slot, int chunk) {
        const long kc = (long)chunk << 5;
        const uint32_t sbase = sm0 + (uint32_t)slot * 30720u;
#pragma unroll
        for (int j = 0; j < 6; ++j) {
            const int s = tid + (j << 8);
            uint32_t dst; const __nv_bfloat16* src;
            if (s < 1024) {
                const int w = s & 511;
                const int row = w >> 2, cs = w & 3;
                const __nv_bfloat16* base = (s < 512) ? Ahp : Alp;
                dst = sbase + ((s < 512) ? 0u : 10240u) + (uint32_t)(row * 80 + cs * 16);
                src = base + (bm + row) * (long)NN + kc + cs * 8;
            } else {
                const int w = s & 255;
                const int row = w >> 2, cs = w & 3;
                const __nv_bfloat16* base = (s < 1280) ? Bhp : Blp;
                dst = sbase + ((s < 1280) ? 20480u : 25600u) + (uint32_t)(row * 80 + cs * 16);
                src = base + (long)(bn + row) * NN + kc + cs * 8;
            }
            CP16(dst, src);
        }
        CP_COMMIT();
    };

    issue(0, 0);
    issue(1, 1);

    const int NITER = 128;
    for (int i = 0; i < NITER; ++i) {
        CP_WAIT1();                 // stage i complete (all groups but newest)
        __syncthreads();
        if (i + 2 < NITER) issue((i + 2) % 3, i + 2);
        else CP_COMMIT();           // keep group numbering aligned

        const uint32_t sbase = sm0 + (uint32_t)(i % 3) * 30720u;
        const uint32_t aH = sbase + aOff;
        const uint32_t aL = sbase + 10240u + aOff;
        const uint32_t bH = sbase + 20480u + bOff;
        const uint32_t bL = sbase + 25600u + bOff;
#pragma unroll
        for (int ks = 0; ks < 2; ++ks) {
            uint32_t ah[2][4], al[2][4], bh[2][4], bl[2][4];
            const uint32_t ko = (uint32_t)(ks * 16 * 2);
            LDM_X4(ah[0][0], ah[0][1], ah[0][2], ah[0][3], aH + ko);
            LDM_X4(ah[1][0], ah[1][1], ah[1][2], ah[1][3], aH + 16u * 80u + ko);
            LDM_X4(al[0][0], al[0][1], al[0][2], al[0][3], aL + ko);
            LDM_X4(al[1][0], al[1][1], al[1][2], al[1][3], aL + 16u * 80u + ko);
            LDM_X4(bh[0][0], bh[0][1], bh[0][2], bh[0][3], bH + ko);
            LDM_X4(bh[1][0], bh[1][1], bh[1][2], bh[1][3], bH + 16u * 80u + ko);
            LDM_X4(bl[0][0], bl[0][1], bl[0][2], bl[0][3], bL + ko);
            LDM_X4(bl[1][0], bl[1][1], bl[1][2], bl[1][3], bL + 16u * 80u + ko);
#pragma unroll
            for (int mi = 0; mi < 2; ++mi) {
#pragma unroll
                for (int nj = 0; nj < 4; ++nj) {
                    const int g = nj >> 1, h = (nj & 1) * 2;
                    MMA16816(acc[mi][nj], ah[mi], bh[g][h], bh[g][h + 1]);
                    MMA16816(acc[mi][nj], ah[mi], bl[g][h], bl[g][h + 1]);
                    MMA16816(acc[mi][nj], al[mi], bh[g][h], bh[g][h + 1]);
                }
            }
        }
        __syncthreads();
    }

    // epilogue
#pragma unroll
    for (int mi = 0; mi < 2; ++mi) {
#pragma unroll
        for (int nj = 0; nj < 4; ++nj) {
            const long row0 = bm + wm * 32 + mi * 16 + (lane >> 2);
            const int  col  = bn + wn * 32 + nj * 8 + (lane & 3) * 2;
            float2 v0 = make_float2(acc[mi][nj][0], acc[mi][nj][1]);
            float2 v1 = make_float2(acc[mi][nj][2], acc[mi][nj][3]);
            if (act) {
                v0.x = fmaxf(v0.x, 0.f); v0.y = fmaxf(v0.y, 0.f);
                v1.x = fmaxf(v1.x, 0.f); v1.y = fmaxf(v1.y, 0.f);
            }
            *(float2*)&C[row0 * (long)F + col]       = v0;
            *(float2*)&C[(row0 + 8) * (long)F + col] = v1;
        }
    }
}

// ---------------- conversion kernels ----------------------------------------
__global__ void asplit(const float* __restrict__ A,
                       __nv_bfloat16* __restrict__ Ah, __nv_bfloat16* __restrict__ Al)
{
    long i = ((long)blockIdx.x * 256 + threadIdx.x) * 4;
    float4 v = *(const float4*)(A + i);
    __nv_bfloat16 h0 = __float2bfloat16(v.x), h1 = __float2bfloat16(v.y);
    __nv_bfloat16 h2 = __float2bfloat16(v.z), h3 = __float2bfloat16(v.w);
    __nv_bfloat162 hh0(h0, h1), hh1(h2, h3);
    *(__nv_bfloat162*)(Ah + i)     = hh0;
    *(__nv_bfloat162*)(Ah + i + 2) = hh1;
    __nv_bfloat162 ll0(__float2bfloat16(v.x - __bfloat162float(h0)),
                       __float2bfloat16(v.y - __bfloat162float(h1)));
    __nv_bfloat162 ll1(__float2bfloat16(v.z - __bfloat162float(h2)),
                       __float2bfloat16(v.w - __bfloat162float(h3)));
    *(__nv_bfloat162*)(Al + i)     = ll0;
    *(__nv_bfloat162*)(Al + i + 2) = ll1;
}

__global__ void tsplit(const float* __restrict__ Y,
                       __nv_bfloat16* __restrict__ Bh, __nv_bfloat16* __restrict__ Bl)
{
    __shared__ float tb[32][33];
    const int k0 = blockIdx.x * 32, n0 = blockIdx.y * 32;
    const int tx = threadIdx.x & 31, ty = threadIdx.x >> 5;
#pragma unroll
    for (int r = ty; r < 32; r += 8)
        tb[r][tx] = Y[(long)(k0 + r) * F + n0 + tx];
    __syncthreads();
#pragma unroll
    for (int c = ty; c < 32; c += 8) {
        float v = tb[tx][c];
        __nv_bfloat16 h = __float2bfloat16(v);
        Bh[(long)(n0 + c) * NN + k0 + tx] = h;
        Bl[(long)(n0 + c) * NN + k0 + tx] = __float2bfloat16(v - __bfloat162float(h));
    }
}

// ---------------- big GEMM: 128x64 tile, FFMA2, double-buffered -------------
__global__ void __launch_bounds__(256, 2) gemm_big(
    const float* __restrict__ Ab, const float* __restrict__ Bb, float* __restrict__ Cb,
    int K, int lda, int ldb, int ldc,
    long sA_, long sB_, long sC_, int act, int mode)
{
    const int z = blockIdx.z;
    const float* A; const float* B; float* C;
    if (mode == 0)      { A = Ab + z * sA_; B = Bb + z * sB_; C = Cb + z * sC_; }
    else if (mode == 1) { A = Ab + (long)(z >> 3) * sA_; B = Bb + (long)(z & 7) * sB_; C = Cb + (long)z * sC_; }
    else                { int t = z >> 3, s = z & 7;
                          A = Ab + (long)t * sA_ + (long)s * K;
                          B = Bb + (long)t * sB_ + (long)s * K * ldb;
                          C = Cb + (long)z * sC_; }

    __shared__ float As[2][16][136];
    __shared__ float Bs[2][16][64];

    const int tid = threadIdx.x;
    const int tx = tid & 15, ty = tid >> 4;
    const long bm = (long)blockIdx.y << 7;
    const int  bn = blockIdx.x << 6;

    const int a_row = tid >> 2;
    const int a_kc  = (tid & 3) << 2;
    const int b_kr  = tid >> 4;
    const int b_kc  = (tid & 15) << 2;

    const float* Ap0 = A + (bm + a_row) * (long)lda + a_kc;
    const float* Ap1 = Ap0 + (long)64 * lda;
    const float* Bp  = B + (long)b_kr * ldb + bn + b_kc;

    {
        float4 va0 = *(const float4*)Ap0;
        float4 va1 = *(const float4*)Ap1;
        float4 vb  = *(const float4*)Bp;
        As[0][a_kc+0][a_row] = va0.x; As[0][a_kc+1][a_row] = va0.y;
        As[0][a_kc+2][a_row] = va0.z; As[0][a_kc+3][a_row] = va0.w;
        As[0][a_kc+0][a_row+64] = va1.x; As[0][a_kc+1][a_row+64] = va1.y;
        As[0][a_kc+2][a_row+64] = va1.z; As[0][a_kc+3][a_row+64] = va1.w;
        *(float4*)&Bs[0][b_kr][b_kc] = vb;
    }
    __syncthreads();

    ull acc[4][4];
#pragma unroll
    for (int p = 0; p < 4; p++)
#pragma unroll
        for (int j = 0; j < 4; j++) acc[p][j] = 0ULL;

    const int nIter = K >> 4;
    int buf = 0;
    for (int it = 0; it < nIter; ++it) {
        float4 na0, na1, nb;
        const bool more = (it + 1 < nIter);
        if (more) {
            na0 = *(const float4*)(Ap0 + (it + 1) * 16);
            na1 = *(const float4*)(Ap1 + (it + 1) * 16);
            nb  = *(const float4*)(Bp + (long)(it + 1) * 16 * ldb);
        }
#pragma unroll
        for (int k = 0; k < 16; ++k) {
            ull a0 = *(const ull*)&As[buf][k][(ty<<3) + 0];
            ull a1 = *(const ull*)&As[buf][k][(ty<<3) + 2];
            ull a2 = *(const ull*)&As[buf][k][(ty<<3) + 4];
            ull a3 = *(const ull*)&As[buf][k][(ty<<3) + 6];
            float4 bv = *(const float4*)&Bs[buf][k][tx<<2];
            ull b0 = pk2(bv.x, bv.x), b1 = pk2(bv.y, bv.y);
            ull b2 = pk2(bv.z, bv.z), b3 = pk2(bv.w, bv.w);
            FMA2(acc[0][0], a0, b0); FMA2(acc[0][1], a0, b1); FMA2(acc[0][2], a0, b2); FMA2(acc[0][3], a0, b3);
            FMA2(acc[1][0], a1, b0); FMA2(acc[1][1], a1, b1); FMA2(acc[1][2], a1, b2); FMA2(acc[1][3], a1, b3);
            FMA2(acc[2][0], a2, b0); FMA2(acc[2][1], a2, b1); FMA2(acc[2][2], a2, b2); FMA2(acc[2][3], a2, b3);
            FMA2(acc[3][0], a3, b0); FMA2(acc[3][1], a3, b1); FMA2(acc[3][2], a3, b2); FMA2(acc[3][3], a3, b3);
        }
        if (more) {
            const int nbuf = buf ^ 1;
            As[nbuf][a_kc+0][a_row] = na0.x; As[nbuf][a_kc+1][a_row] = na0.y;
            As[nbuf][a_kc+2][a_row] = na0.z; As[nbuf][a_kc+3][a_row] = na0.w;
            As[nbuf][a_kc+0][a_row+64] = na1.x; As[nbuf][a_kc+1][a_row+64] = na1.y;
            As[nbuf][a_kc+2][a_row+64] = na1.z; As[nbuf][a_kc+3][a_row+64] = na1.w;
            *(float4*)&Bs[nbuf][b_kr][b_kc] = nb;
        }
        __syncthreads();
        buf ^= 1;
    }

#pragma unroll
    for (int p = 0; p < 4; ++p) {
        float4 vlo = make_float4(lo32(acc[p][0]), lo32(acc[p][1]), lo32(acc[p][2]), lo32(acc[p][3]));
        float4 vhi = make_float4(hi32(acc[p][0]), hi32(acc[p][1]), hi32(acc[p][2]), hi32(acc[p][3]));
        if (act) {
            vlo.x = fmaxf(vlo.x, 0.f); vlo.y = fmaxf(vlo.y, 0.f);
            vlo.z = fmaxf(vlo.z, 0.f); vlo.w = fmaxf(vlo.w, 0.f);
            vhi.x = fmaxf(vhi.x, 0.f); vhi.y = fmaxf(vhi.y, 0.f);
            vhi.z = fmaxf(vhi.z, 0.f); vhi.w = fmaxf(vhi.w, 0.f);
        }
        long r = bm + (ty << 3) + (p << 1);
        *(float4*)&C[r * (long)ldc + bn + (tx << 2)]       = vlo;
        *(float4*)&C[(r + 1) * (long)ldc + bn + (tx << 2)] = vhi;
    }
}

// ---------------- persistent GRU chain --------------------------------------
__device__ __forceinline__ void grid_bar(unsigned* ctr, unsigned nblk) {
    __syncthreads();
    if (threadIdx.x == 0) {
        __threadfence();
        unsigned prev = atomicAdd(ctr, 1u);
        if (prev + 1u < nblk) {
            while (*(volatile unsigned*)ctr < nblk) { }
        }
        __threadfence();
    }
    __syncthreads();
}

__device__ __forceinline__ void tile32(
    const float* __restrict__ gA, const float* __restrict__ gB,
    float (*As)[16][36], float (*Bs)[16][36], ull* acc)
{
    const int tid = threadIdx.x;
    const int ty = tid >> 4, tx = tid & 15;
    acc[0] = 0ULL; acc[1] = 0ULL;

    const int la_r = tid >> 2;
    const int la_k = (tid & 3) << 2;
    const int lb_u = tid & 127;
    const int lb_k = lb_u >> 3;
    const int lb_n = (lb_u & 7) << 2;

    {
        float4 v;
        if (tid < 128) {
            v = *(const float4*)(gA + la_r * F + la_k);
            As[0][la_k+0][la_r] = v.x; As[0][la_k+1][la_r] = v.y;
            As[0][la_k+2][la_r] = v.z; As[0][la_k+3][la_r] = v.w;
        } else {
            v = *(const float4*)(gB + lb_k * F + lb_n);
            *(float4*)&Bs[0][lb_k][lb_n] = v;
        }
    }
    __syncthreads();

    int buf = 0;
    for (int it = 0; it < 16; ++it) {
        float4 nv;
        const bool more = (it < 15);
        if (more) {
            int k0 = (it + 1) << 4;
            if (tid < 128) nv = *(const float4*)(gA + la_r * F + k0 + la_k);
            else           nv = *(const float4*)(gB + (k0 + lb_k) * F + lb_n);
        }
#pragma unroll
        for (int k = 0; k < 16; ++k) {
            ull av = *(const ull*)&As[buf][k][ty << 1];
            ull bv = *(const ull*)&Bs[buf][k][tx << 1];
            float b0 = lo32(bv), b1 = hi32(bv);
            ull bb0 = pk2(b0, b0);
            ull bb1 = pk2(b1, b1);
            FMA2(acc[0], av, bb0);
            FMA2(acc[1], av, bb1);
        }
        if (more) {
            const int nb = buf ^ 1;
            if (tid < 128) {
                As[nb][la_k+0][la_r] = nv.x; As[nb][la_k+1][la_r] = nv.y;
                As[nb][la_k+2][la_r] = nv.z; As[nb][la_k+3][la_r] = nv.w;
            } else {
                *(float4*)&Bs[nb][lb_k][lb_n] = nv;
            }
        }
        __syncthreads();
        buf ^= 1;
    }
}

__device__ __forceinline__ float sigf(float x) { return 1.0f / (1.0f + expf(-x)); }

__global__ void __launch_bounds__(256, 1) gru_chain(
    const float* __restrict__ Uz, const float* __restrict__ Ur, const float* __restrict__ Uh,
    const float* __restrict__ P,
    const float* __restrict__ bz, const float* __restrict__ br, const float* __restrict__ bh,
    const float* __restrict__ Q0, float* __restrict__ Q,
    float* __restrict__ upd, float* __restrict__ RQ,
    float* __restrict__ Qseq, unsigned* __restrict__ bar)
{
    __shared__ float As[2][16][36];
    __shared__ float Bs[2][16][36];

    const int tid = threadIdx.x;
    const int bid = blockIdx.x;
    const int gate = bid >> 6;
    const int id   = bid & 63;
    const int tm   = id >> 3;
    const int tn   = id & 7;
    const int ty = tid >> 4, tx = tid & 15;
    const int rb = tm * 32 + (ty << 1);
    const int cb = tn * 32 + (tx << 1);

    for (int t = 0; t < T; ++t) {
        const float* Qprev = (t == 0) ? Q0 : Q;

        {
            const float* Amat = gate ? Ur : Uz;
            const float* Pg   = P + (long)((gate ? T : 0) + t) * FF;
            const float* bb   = gate ? br : bz;
            ull acc[2];
            tile32(Amat + (long)tm * 32 * F, Qprev + tn * 32, As, Bs, acc);
#pragma unroll
            for (int j = 0; j < 2; ++j) {
#pragma unroll
                for (int e = 0; e < 2; ++e) {
                    long idx = (long)(rb + e) * F + cb + j;
                    float a = e ? hi32(acc[j]) : lo32(acc[j]);
                    float s = sigf(a + Pg[idx] + bb[idx]);
                    if (!gate) upd[idx] = s;
                    else       RQ[idx] = s * Qprev[idx];
                }
            }
        }
        grid_bar(bar + 2 * t, GRU_GRID);

        if (bid < 64) {
            const float* Ph = P + (long)(2 * T + t) * FF;
            ull acc[2];
            tile32(Uh + (long)tm * 32 * F, RQ + tn * 32, As, Bs, acc);
#pragma unroll
            for (int j = 0; j < 2; ++j) {
#pragma unroll
                for (int e = 0; e < 2; ++e) {
                    long idx = (long)(rb + e) * F + cb + j;
                    float a = e ? hi32(acc[j]) : lo32(acc[j]);
                    float h = tanhf(a + Ph[idx] + bh[idx]);
                    float u = upd[idx];
                    float q = (1.0f - u) * Qprev[idx] + u * h;
                    Q[idx] = q;
                    if (Qseq) Qseq[(long)t * FF + idx] = q;
                }
            }
        }
        grid_bar(bar + 2 * t + 1, GRU_GRID);
    }
}

// ---------------- scores + transposed zt ------------------------------------
__global__ void score_kernel(const float* __restrict__ embs, long stride, int ld,
                             const float* __restrict__ scorer, float* __restrict__ th)
{
    const int t = blockIdx.x;
    const float* E = embs + (long)t * stride;
    __shared__ float sc[F];
    __shared__ float red[256];
    const int tid = threadIdx.x;
    float s = scorer[tid];
    sc[tid] = s;
    red[tid] = s * s;
    __syncthreads();
    for (int off = 128; off > 0; off >>= 1) {
        if (tid < off) red[tid] += red[tid + off];
        __syncthreads();
    }
    const float inv_sn = 1.0f / sqrtf(red[0]);
    float dot = 0.f;
    const float* row = E + (long)tid * ld;
#pragma unroll 8
    for (int c = 0; c < F; c++) dot += row[c] * sc[c];
    th[t * F + tid] = tanhf(dot * inv_sn);
}

__global__ void zt_trans(const float* __restrict__ embs, long stride, int ld,
                         const float* __restrict__ th, float* __restrict__ zt)
{
    const int t = blockIdx.y;
    const int tile = blockIdx.x;
    const int ti = tile >> 3, tj = tile & 7;
    const float* E = embs + (long)t * stride;
    float* Z = zt + (long)t * FF;

    __shared__ float tb[32][33];
    const int tx = threadIdx.x & 31;
    const int ty8 = threadIdx.x >> 5;

#pragma unroll
    for (int r0 = 0; r0 < 4; ++r0) {
        int r = ty8 + (r0 << 3);
        tb[r][tx] = E[(long)(ti * 32 + r) * ld + tj * 32 + tx] * th[t * F + ti * 32 + r];
    }
    __syncthreads();
#pragma unroll
    for (int c0 = 0; c0 < 4; ++c0) {
        int c = ty8 + (c0 << 3);
        Z[(long)(tj * 32 + c) * F + ti * 32 + tx] = tb[tx][c];
    }
}

// ---------------- misc -------------------------------------------------------
__global__ void reduce_relu(const float* __restrict__ part, float* __restrict__ out)
{
    long i = (long)blockIdx.x * 256 + threadIdx.x;
    long t = i >> 16;
    long r = i & (FF - 1);
    const float* p = part + t * (long)(NSPLIT * FF) + r;
    float s = 0.f;
#pragma unroll
    for (int j = 0; j < NSPLIT; ++j) s += p[(long)j * FF];
    out[i] = fmaxf(s, 0.0f);
}

__global__ void pack3(const float* __restrict__ a, const float* __restrict__ b,
                      const float* __restrict__ c, float* __restrict__ dst)
{
    int i = blockIdx.x * 256 + threadIdx.x;
    dst[i] = a[i]; dst[FF + i] = b[i]; dst[2 * FF + i] = c[i];
}

__global__ void copy1(const float* __restrict__ src, float* __restrict__ dst)
{
    int i = blockIdx.x * 256 + threadIdx.x;
    dst[i] = src[i];
}

__global__ void zero_bar(unsigned* b) { b[threadIdx.x] = 0u; }

// ---------------------------------------------------------------------------
extern "C" void kernel_launch(void* const* d_in, const int* in_sizes, int n_in,
                              void* d_out, int out_size)
{
    const float* Aadj = (const float*)d_in[0];
    const float* X    = (const float*)d_in[1];
    auto LP = [&](int l, int idx) { return (const float*)d_in[3 + l * 11 + idx]; };

    float *zt, *P, *Q, *Qseq, *W3, *upd, *RQ, *th, *Y, *part, *h1top, *h1full, *Z;
    unsigned* bar;
    __nv_bfloat16 *Ah, *Al, *Bh, *Bl;
    cudaGetSymbolAddress((void**)&zt,     g_zt);
    cudaGetSymbolAddress((void**)&P,      g_P);
    cudaGetSymbolAddress((void**)&Q,      g_Q);
    cudaGetSymbolAddress((void**)&Qseq,   g_Qseq);
    cudaGetSymbolAddress((void**)&W3,     g_W3);
    cudaGetSymbolAddress((void**)&upd,    g_upd);
    cudaGetSymbolAddress((void**)&RQ,     g_RQ);
    cudaGetSymbolAddress((void**)&th,     g_th);
    cudaGetSymbolAddress((void**)&Y,      g_Y);
    cudaGetSymbolAddress((void**)&part,   g_part);
    cudaGetSymbolAddress((void**)&h1top,  g_h1top);
    cudaGetSymbolAddress((void**)&h1full, g_h1full);
    cudaGetSymbolAddress((void**)&Z,      g_Z);
    cudaGetSymbolAddress((void**)&bar,    g_bar);
    cudaGetSymbolAddress((void**)&Ah,     g_Ah);
    cudaGetSymbolAddress((void**)&Al,     g_Al);
    cudaGetSymbolAddress((void**)&Bh,     g_Bh);
    cudaGetSymbolAddress((void**)&Bl,     g_Bl);

    cudaFuncSetAttribute(gemm_mma, cudaFuncAttributeMaxDynamicSharedMemorySize, 92160);

    zero_bar<<<1, 64>>>(bar);
    asplit<<<(int)(((long)NN * NN / 4) / 256), 256>>>(Aadj + 7L * NN * NN, Ah, Al);

    for (int l = 0; l < 2; ++l) {
        const float* embs = (l == 0) ? X : h1top;
        long estride = (l == 0) ? (long)NF : (long)FF;

        score_kernel<<<T, 256>>>(embs, estride, F, LP(l, 0), th);
        zt_trans<<<dim3(64, T), 256>>>(embs, estride, F, th, zt);

        pack3<<<FF / 256, 256>>>(LP(l, 1), LP(l, 4), LP(l, 7), W3);
        gemm_big<<<dim3(4, 2, 24), 256>>>(W3, zt, P, F, F, F, F,
                                          (long)FF, (long)FF, (long)FF, 0, 1);

        gru_chain<<<GRU_GRID, 256>>>(LP(l, 2), LP(l, 5), LP(l, 8), P,
                                     LP(l, 3), LP(l, 6), LP(l, 9),
                                     LP(l, 10), Q, upd, RQ,
                                     (l == 0) ? Qseq : nullptr,
                                     bar + l * 32);

        if (l == 0) {
            gemm_big<<<dim3(4, 32, 8), 256>>>(X, Qseq, Y, F, F, F, F,
                                              (long)NF, (long)FF, (long)NF, 0, 0);
            gemm_big<<<dim3(4, 2, 56), 256>>>(Aadj, Y, part, NN / NSPLIT, NN, F, F,
                                              (long)NN * NN, (long)NF, (long)FF, 0, 2);
            reduce_relu<<<7 * FF / 256, 256>>>(part, h1top);
            tsplit<<<dim3(128, 8), 256>>>(Y + 7L * NF, Bh, Bl);
            gemm_mma<<<dim3(4, 32), 256, 92160>>>(Ah, Al, Bh, Bl, h1full, 1);
            copy1<<<FF / 256, 256>>>(h1full, h1top + 7L * FF);
        }
    }

    gemm_big<<<dim3(4, 32, 1), 256>>>(h1full, Q, Z, F, F, F, F, 0, 0, 0, 0, 0);
    tsplit<<<dim3(128, 8), 256>>>(Z, Bh, Bl);
    gemm_mma<<<dim3(4, 32), 256, 92160>>>(Ah, Al, Bh, Bl, (float*)d_out, 1);
}